// round 5
// baseline (speedup 1.0000x reference)
#include <cuda_runtime.h>
#include <math.h>

#define Bsz 4
#define C 64
#define H 128
#define W 128
#define N 16384   // H*W per batch
#define OC 89
#define YP 36     // [c][p] tile pitch for 32 positions (mult of 4)

// scratch (__device__ globals; allocation is forbidden)
__device__ float g_lat_t[Bsz * N * C];    // latents channels-last [b][p][c]
__device__ float g_qf[Bsz * N * C];       // bilinear-sampled features [b][n][c]
__device__ float g_qkvo[Bsz * N * 192];   // per row: q[0:64] | k[64:128] | vo[128:192]
// folded weights, chunk-interleaved: g_Wt2[(c>>2)*192*4 + j*4 + (c&3)] = W'[c][j]
__device__ float g_Wt2[16 * 192 * 4];
__device__ float g_bc[192];               // folded bias

// ---------------- f32x2 helpers (sm_103a packed fp32) ----------------------
__device__ __forceinline__ void ffma2(unsigned long long& d,
                                      unsigned long long a,
                                      unsigned long long b) {
    asm("fma.rn.f32x2 %0, %1, %2, %0;" : "+l"(d) : "l"(a), "l"(b));
}
__device__ __forceinline__ unsigned long long f2_to_ull(float x, float y) {
    unsigned long long r;
    asm("mov.b64 %0, {%1, %2};" : "=l"(r) : "f"(x), "f"(y));
    return r;
}
__device__ __forceinline__ unsigned long long dup_f32(float v) {
    unsigned long long r;
    asm("mov.b64 %0, {%1, %1};" : "=l"(r) : "f"(v));
    return r;
}
__device__ __forceinline__ float2 ull_to_f2(unsigned long long v) {
    float2 r;
    asm("mov.b64 {%0, %1}, %2;" : "=f"(r.x), "=f"(r.y) : "l"(v));
    return r;
}

// ---------------------------------------------------------------------------
// K0: transpose latents [b][c][p] -> [b][p][c]
// ---------------------------------------------------------------------------
__global__ void k_transpose(const float* __restrict__ lat) {
    __shared__ float s[64][65];
    int b  = blockIdx.x >> 8;
    int pb = (blockIdx.x & 255) * 64;
    int tid = threadIdx.x;
    const float* src = lat + (size_t)b * N * C;
    {
        int pq = tid & 63, cg = tid >> 6;
        #pragma unroll
        for (int k = 0; k < 16; k++) {
            int c = cg * 16 + k;
            s[c][pq] = src[(size_t)c * N + pb + pq];
        }
    }
    __syncthreads();
    float* dst = g_lat_t + (size_t)b * N * C;
    {
        int cl = tid & 63, pg = tid >> 6;
        #pragma unroll
        for (int k = 0; k < 16; k++) {
            int p = pg * 16 + k;
            dst[(size_t)(pb + p) * C + cl] = s[cl][p];
        }
    }
}

// ---------------------------------------------------------------------------
// K1: bilinear sample of latents. One warp per point.
// ---------------------------------------------------------------------------
__global__ void k_sample_lat(const float* __restrict__ coords) {
    int gwarp = (blockIdx.x * blockDim.x + threadIdx.x) >> 5;
    int lane  = threadIdx.x & 31;
    if (gwarp >= Bsz * N) return;
    int b = gwarp >> 14;

    float y = coords[(size_t)gwarp * 2 + 0];   // xy = flip(coords)
    float x = coords[(size_t)gwarp * 2 + 1];
    float ix = ((x + 1.f) * (float)W - 1.f) * 0.5f;
    float iy = ((y + 1.f) * (float)H - 1.f) * 0.5f;
    float x0f = floorf(ix), y0f = floorf(iy);
    float wx1 = ix - x0f, wy1 = iy - y0f;
    int x0 = (int)x0f, y0 = (int)y0f;

    const float* base = g_lat_t + (size_t)b * N * C;
    float2 acc = make_float2(0.f, 0.f);
    #pragma unroll
    for (int dy = 0; dy < 2; dy++) {
        #pragma unroll
        for (int dx = 0; dx < 2; dx++) {
            int xc = x0 + dx, yc = y0 + dy;
            float wgt = (dx ? wx1 : 1.f - wx1) * (dy ? wy1 : 1.f - wy1);
            bool valid = (xc >= 0) && (xc < W) && (yc >= 0) && (yc < H);
            int xi = min(max(xc, 0), W - 1);
            int yi = min(max(yc, 0), H - 1);
            float wv = valid ? wgt : 0.f;
            float2 t = ((const float2*)(base + ((size_t)yi * W + xi) * C))[lane];
            acc.x += wv * t.x;
            acc.y += wv * t.y;
        }
    }
    ((float2*)(g_qf + (size_t)gwarp * C))[lane] = acc;
}

// ---------------------------------------------------------------------------
// k_prep: one block per output column j (192 blocks, 64 threads).
// ---------------------------------------------------------------------------
__global__ void k_prep(const float* __restrict__ w_q,
                       const float* __restrict__ w_kv,
                       const float* __restrict__ w_out,
                       const float* __restrict__ lnq_s,
                       const float* __restrict__ lnq_b,
                       const float* __restrict__ lnc_s,
                       const float* __restrict__ lnc_b) {
    __shared__ float red[64];
    int j = blockIdx.x;
    int c = threadIdx.x;    // 0..63

    float m;
    float lns, lnb;
    if (j < 64) {
        m = w_q[c * 64 + j];
        lns = lnq_s[c]; lnb = lnq_b[c];
    } else if (j < 128) {
        m = w_kv[c * 128 + (j - 64)];
        lns = lnc_s[c]; lnb = lnc_b[c];
    } else {
        float s = 0.f;
        int jj = j - 128;
        #pragma unroll 8
        for (int t = 0; t < 64; t++)
            s += w_kv[c * 128 + 64 + t] * w_out[t * 64 + jj];
        m = s;
        lns = lnc_s[c]; lnb = lnc_b[c];
    }
    g_Wt2[(c >> 2) * 768 + j * 4 + (c & 3)] = lns * m;

    red[c] = lnb * m;
    __syncthreads();
    if (c < 32) {
        float v = red[c] + red[c + 32];
        #pragma unroll
        for (int o = 16; o > 0; o >>= 1) v += __shfl_xor_sync(~0u, v, o);
        if (c == 0) g_bc[j] = v;
    }
}

// ---------------------------------------------------------------------------
// K2: qkvo GEMM.  Block = 192 threads (6 warps), 32 positions.
//   Warp tile: 64 cols (lane j, j+32) x 16 positions (8 f32x2 accums/col).
//   Small acc footprint -> 5 blocks/SM (30 warps) for latency hiding.
// ---------------------------------------------------------------------------
__global__ void __launch_bounds__(192, 5) k_qkvo() {
    __shared__ float yq[64 * YP];
    __shared__ float yc[64 * YP];
    int b  = blockIdx.x >> 9;           // 512 blocks per batch
    int pb = (blockIdx.x & 511) * 32;
    int tid = threadIdx.x;

    // yq tile: global rows [p][c] -> smem [c][p]
    const float* qrow = g_qf + ((size_t)b * N + pb) * 64;
    for (int idx = tid; idx < 2048; idx += 192) {
        int p = idx >> 6, c = idx & 63;
        yq[c * YP + p] = qrow[idx];
    }
    // yc tile: flat columns, already [c][p]
    const float* qb = g_qf + (size_t)b * N * 64;
    for (int idx = tid; idx < 2048; idx += 192) {
        int c = idx >> 5, p = idx & 31;
        yc[c * YP + p] = qb[(size_t)c * N + pb + p];
    }
    __syncthreads();

    // LN (normalize only; scale/bias folded into weights)
    if (tid < 64) {
        float* col = ((tid < 32) ? yq : yc) + (tid & 31);
        float s = 0.f, sq = 0.f;
        #pragma unroll 8
        for (int c = 0; c < 64; c++) { float v = col[c * YP]; s += v; sq += v * v; }
        float mu = s * (1.f / 64.f);
        float var = sq * (1.f / 64.f) - mu * mu;
        float rstd = rsqrtf(var + 1e-5f);
        #pragma unroll 8
        for (int c = 0; c < 64; c++) col[c * YP] = (col[c * YP] - mu) * rstd;
    }
    __syncthreads();

    int warp = tid >> 5;        // 0..5
    int lane = tid & 31;
    int wg = warp % 3;          // column group of 64
    int pg = warp / 3;          // position quarter (16 pos)
    int jA = wg * 64 + lane;
    int jB = jA + 32;
    int p0 = pg * 16;
    const float* ybuf = (wg == 0) ? yq : yc;

    unsigned long long accA[8], accB[8];
    {
        unsigned long long bA = dup_f32(__ldg(&g_bc[jA]));
        unsigned long long bB = dup_f32(__ldg(&g_bc[jB]));
        #pragma unroll
        for (int i = 0; i < 8; i++) { accA[i] = bA; accB[i] = bB; }
    }

    #pragma unroll 2
    for (int c4 = 0; c4 < 16; c4++) {
        float4 wA4 = __ldg((const float4*)&g_Wt2[c4 * 768 + jA * 4]);
        float4 wB4 = __ldg((const float4*)&g_Wt2[c4 * 768 + jB * 4]);
        const float* wAp = (const float*)&wA4;
        const float* wBp = (const float*)&wB4;
        #pragma unroll
        for (int k = 0; k < 4; k++) {
            unsigned long long wa = dup_f32(wAp[k]);
            unsigned long long wb = dup_f32(wBp[k]);
            const float4* yp = (const float4*)&ybuf[(c4 * 4 + k) * YP + p0];
            #pragma unroll
            for (int m = 0; m < 4; m++) {
                float4 y4 = yp[m];
                unsigned long long y01 = f2_to_ull(y4.x, y4.y);
                unsigned long long y23 = f2_to_ull(y4.z, y4.w);
                ffma2(accA[2 * m],     y01, wa);
                ffma2(accA[2 * m + 1], y23, wa);
                ffma2(accB[2 * m],     y01, wb);
                ffma2(accB[2 * m + 1], y23, wb);
            }
        }
    }

    float* ob = g_qkvo + ((size_t)b * N + pb + p0) * 192;
    #pragma unroll
    for (int i = 0; i < 8; i++) {
        float2 a = ull_to_f2(accA[i]);
        float2 bv = ull_to_f2(accB[i]);
        ob[(size_t)(2 * i) * 192 + jA]     = a.x;
        ob[(size_t)(2 * i + 1) * 192 + jA] = a.y;
        ob[(size_t)(2 * i) * 192 + jB]     = bv.x;
        ob[(size_t)(2 * i + 1) * 192 + jB] = bv.y;
    }
}

// ---------------------------------------------------------------------------
// K3: attention, 2D-tiled with smem halo.
//   Block = 256 thr (8 warps), tile = 4x8 queries, halo = 6x10 k|vo rows
//   staged in smem (30.7KB). Warp handles 4 queries.
// ---------------------------------------------------------------------------
__global__ void __launch_bounds__(256) k_attn(const float* __restrict__ b_out,
                                              float* __restrict__ out) {
    __shared__ float kv[60 * 128];   // 30720 B
    int tile = blockIdx.x;           // 2048
    int b = tile >> 9;               // 512 tiles per batch
    int t = tile & 511;
    int th = t >> 4;                 // 0..31
    int tw = t & 15;                 // 0..15
    int h0 = th * 4, w0 = tw * 8;
    int tid = threadIdx.x;

    const float* kvb = g_qkvo + (size_t)b * N * 192;
    for (int i = tid; i < 1920; i += 256) {
        int r = i >> 5, q4 = i & 31;
        int ri = r / 10, rj = r % 10;
        int gh = min(max(h0 - 1 + ri, 0), H - 1);
        int gw = min(max(w0 - 1 + rj, 0), W - 1);
        ((float4*)kv)[r * 32 + q4] =
            *(const float4*)(kvb + (size_t)(gh * W + gw) * 192 + 64 + q4 * 4);
    }
    __syncthreads();

    int warp = tid >> 5, lane = tid & 31;
    int qi = warp >> 1;                    // 0..3
    float bo0 = __ldg(&b_out[lane]), bo1 = __ldg(&b_out[lane + 32]);

    #pragma unroll
    for (int q = 0; q < 4; q++) {
        int qj = (warp & 1) * 4 + q;       // 0..7
        int h = h0 + qi, w = w0 + qj;
        int g = b * N + h * W + w;
        const float* row = g_qkvo + (size_t)g * 192;
        float q0 = row[lane], q1 = row[32 + lane];

        int rr[9];
        float e[9];
        #pragma unroll
        for (int k = 0; k < 9; k++) {
            int di = k / 3 - 1, dj = k % 3 - 1;
            int nh = min(max(h + di, 0), H - 1) - h0 + 1;
            int nw = min(max(w + dj, 0), W - 1) - w0 + 1;
            rr[k] = nh * 10 + nw;
            const float* kr = kv + rr[k] * 128;
            float part = q0 * kr[lane] + q1 * kr[32 + lane];
            #pragma unroll
            for (int o = 1; o < 32; o <<= 1) part += __shfl_xor_sync(~0u, part, o);
            e[k] = part * 0.125f;
        }
        float m = e[0];
        #pragma unroll
        for (int k = 1; k < 9; k++) m = fmaxf(m, e[k]);
        float den = 0.f;
        #pragma unroll
        for (int k = 0; k < 9; k++) { e[k] = __expf(e[k] - m); den += e[k]; }
        float inv = 1.f / den;

        float o0 = 0.f, o1 = 0.f;
        #pragma unroll
        for (int k = 0; k < 9; k++) {
            const float* vr = kv + rr[k] * 128 + 64;
            float a = e[k] * inv;
            o0 += a * vr[lane];
            o1 += a * vr[32 + lane];
        }
        out[(size_t)g * OC + lane]      = o0 + bo0;
        out[(size_t)g * OC + 32 + lane] = o1 + bo1;
    }
}

// ---------------------------------------------------------------------------
// K4: tail — image sample, analytic fcoord sample, positional encoding.
// ---------------------------------------------------------------------------
__global__ void k_tail(const float* __restrict__ coords,
                       const float* __restrict__ image,
                       float* __restrict__ out) {
    int g = blockIdx.x * blockDim.x + threadIdx.x;
    if (g >= Bsz * N) return;
    int b = g >> 14;
    float y = coords[(size_t)g * 2 + 0];
    float x = coords[(size_t)g * 2 + 1];

    float ix = ((x + 1.f) * 256.f - 1.f) * 0.5f;
    float iy = ((y + 1.f) * 256.f - 1.f) * 0.5f;
    float x0f = floorf(ix), y0f = floorf(iy);
    float wx = ix - x0f, wy = iy - y0f;
    int x0 = (int)x0f, y0 = (int)y0f;
    const float* img = image + (size_t)b * 256 * 256;

    float ix2 = ((x + 1.f) * 128.f - 1.f) * 0.5f;
    float iy2 = ((y + 1.f) * 128.f - 1.f) * 0.5f;
    float x0f2 = floorf(ix2), y0f2 = floorf(iy2);
    float wx2 = ix2 - x0f2, wy2 = iy2 - y0f2;
    int x02 = (int)x0f2, y02 = (int)y0f2;

    float qin = 0.f, qcy = 0.f, qcx = 0.f;
    #pragma unroll
    for (int dy = 0; dy < 2; dy++) {
        #pragma unroll
        for (int dx = 0; dx < 2; dx++) {
            {
                int xc = x0 + dx, yc = y0 + dy;
                float wgt = (dx ? wx : 1.f - wx) * (dy ? wy : 1.f - wy);
                bool valid = (xc >= 0) && (xc < 256) && (yc >= 0) && (yc < 256);
                int xi = min(max(xc, 0), 255), yi = min(max(yc, 0), 255);
                qin += (valid ? wgt : 0.f) * img[yi * 256 + xi];
            }
            {
                int xc = x02 + dx, yc = y02 + dy;
                float wgt = (dx ? wx2 : 1.f - wx2) * (dy ? wy2 : 1.f - wy2);
                bool valid = (xc >= 0) && (xc < 128) && (yc >= 0) && (yc < 128);
                int xi = min(max(xc, 0), 127), yi = min(max(yc, 0), 127);
                float wv = valid ? wgt : 0.f;
                qcy += wv * (-1.f + (2.f * yi + 1.f) * (1.f / 128.f));
                qcx += wv * (-1.f + (2.f * xi + 1.f) * (1.f / 128.f));
            }
        }
    }

    float* o = out + (size_t)g * OC + 64;
    o[0] = qin;
    float cy = (qcy + 1.f) * 0.5f;
    float cx = (qcx + 1.f) * 0.5f;
    const float PI = 3.14159265358979323846f;
    #pragma unroll
    for (int k = 0; k < 6; k++) {
        float f = (float)(1 << k) * PI;
        float sy, cvy, sx, cvx;
        sincosf(cy * f, &sy, &cvy);
        sincosf(cx * f, &sx, &cvx);
        o[1 + k]          = sy;
        o[1 + 6 + k]      = sx;
        o[1 + 12 + k]     = cvy;
        o[1 + 12 + 6 + k] = cvx;
    }
}

extern "C" void kernel_launch(void* const* d_in, const int* in_sizes, int n_in,
                              void* d_out, int out_size) {
    const float* image   = (const float*)d_in[0];
    const float* latents = (const float*)d_in[1];
    const float* coords  = (const float*)d_in[2];
    const float* lnq_s   = (const float*)d_in[3];
    const float* lnq_b   = (const float*)d_in[4];
    const float* lnc_s   = (const float*)d_in[5];
    const float* lnc_b   = (const float*)d_in[6];
    const float* w_q     = (const float*)d_in[7];
    const float* w_kv    = (const float*)d_in[8];
    const float* w_out   = (const float*)d_in[9];
    const float* b_out   = (const float*)d_in[10];
    float* out = (float*)d_out;

    k_prep      <<<192, 64>>>(w_q, w_kv, w_out, lnq_s, lnq_b, lnc_s, lnc_b);
    k_transpose <<<1024, 256>>>(latents);
    k_sample_lat<<<8192, 256>>>(coords);
    k_qkvo      <<<2048, 192>>>();
    k_attn      <<<2048, 256>>>(b_out, out);
    k_tail      <<<256, 256>>>(coords, image, out);
}

// round 6
// speedup vs baseline: 1.0027x; 1.0027x over previous
#include <cuda_runtime.h>
#include <math.h>

#define Bsz 4
#define C 64
#define H 128
#define W 128
#define N 16384   // H*W per batch
#define OC 89
#define YPAD 68   // [c][p] tile pitch (floats) for 64 positions

// scratch (__device__ globals; allocation is forbidden)
__device__ float g_lat_t[Bsz * N * C];    // latents channels-last [b][p][c]
__device__ float g_qf[Bsz * N * C];       // bilinear-sampled features [b][n][c]
__device__ float g_qkvo[Bsz * N * 192];   // per row: q[0:64] | k[64:128] | vo[128:192]
// folded weights, chunk-interleaved: g_Wt2[(c>>2)*192*4 + j*4 + (c&3)] = W'[c][j]
__device__ float g_Wt2[16 * 192 * 4];
__device__ float g_bc[192];               // folded bias

// ---------------- f32x2 helpers (sm_103a packed fp32) ----------------------
__device__ __forceinline__ void ffma2(unsigned long long& d,
                                      unsigned long long a,
                                      unsigned long long b) {
    asm("fma.rn.f32x2 %0, %1, %2, %0;" : "+l"(d) : "l"(a), "l"(b));
}
__device__ __forceinline__ unsigned long long f2_to_ull(float x, float y) {
    unsigned long long r;
    asm("mov.b64 %0, {%1, %2};" : "=l"(r) : "f"(x), "f"(y));
    return r;
}
__device__ __forceinline__ unsigned long long dup_f32(float v) {
    unsigned long long r;
    asm("mov.b64 %0, {%1, %1};" : "=l"(r) : "f"(v));
    return r;
}
__device__ __forceinline__ float2 ull_to_f2(unsigned long long v) {
    float2 r;
    asm("mov.b64 {%0, %1}, %2;" : "=f"(r.x), "=f"(r.y) : "l"(v));
    return r;
}

// ---------------------------------------------------------------------------
// K0: transpose latents [b][c][p] -> [b][p][c]
// ---------------------------------------------------------------------------
__global__ void k_transpose(const float* __restrict__ lat) {
    __shared__ float s[64][65];
    int b  = blockIdx.x >> 8;
    int pb = (blockIdx.x & 255) * 64;
    int tid = threadIdx.x;
    const float* src = lat + (size_t)b * N * C;
    {
        int pq = tid & 63, cg = tid >> 6;
        #pragma unroll
        for (int k = 0; k < 16; k++) {
            int c = cg * 16 + k;
            s[c][pq] = src[(size_t)c * N + pb + pq];
        }
    }
    __syncthreads();
    float* dst = g_lat_t + (size_t)b * N * C;
    {
        int cl = tid & 63, pg = tid >> 6;
        #pragma unroll
        for (int k = 0; k < 16; k++) {
            int p = pg * 16 + k;
            dst[(size_t)(pb + p) * C + cl] = s[cl][p];
        }
    }
}

// ---------------------------------------------------------------------------
// K1: bilinear sample of latents. One warp per point.
// ---------------------------------------------------------------------------
__global__ void k_sample_lat(const float* __restrict__ coords) {
    int gwarp = (blockIdx.x * blockDim.x + threadIdx.x) >> 5;
    int lane  = threadIdx.x & 31;
    if (gwarp >= Bsz * N) return;
    int b = gwarp >> 14;

    float y = coords[(size_t)gwarp * 2 + 0];   // xy = flip(coords)
    float x = coords[(size_t)gwarp * 2 + 1];
    float ix = ((x + 1.f) * (float)W - 1.f) * 0.5f;
    float iy = ((y + 1.f) * (float)H - 1.f) * 0.5f;
    float x0f = floorf(ix), y0f = floorf(iy);
    float wx1 = ix - x0f, wy1 = iy - y0f;
    int x0 = (int)x0f, y0 = (int)y0f;

    const float* base = g_lat_t + (size_t)b * N * C;
    float2 acc = make_float2(0.f, 0.f);
    #pragma unroll
    for (int dy = 0; dy < 2; dy++) {
        #pragma unroll
        for (int dx = 0; dx < 2; dx++) {
            int xc = x0 + dx, yc = y0 + dy;
            float wgt = (dx ? wx1 : 1.f - wx1) * (dy ? wy1 : 1.f - wy1);
            bool valid = (xc >= 0) && (xc < W) && (yc >= 0) && (yc < H);
            int xi = min(max(xc, 0), W - 1);
            int yi = min(max(yc, 0), H - 1);
            float wv = valid ? wgt : 0.f;
            float2 t = ((const float2*)(base + ((size_t)yi * W + xi) * C))[lane];
            acc.x += wv * t.x;
            acc.y += wv * t.y;
        }
    }
    ((float2*)(g_qf + (size_t)gwarp * C))[lane] = acc;
}

// ---------------------------------------------------------------------------
// k_prep: one block per output column j (192 blocks, 64 threads).
// ---------------------------------------------------------------------------
__global__ void k_prep(const float* __restrict__ w_q,
                       const float* __restrict__ w_kv,
                       const float* __restrict__ w_out,
                       const float* __restrict__ lnq_s,
                       const float* __restrict__ lnq_b,
                       const float* __restrict__ lnc_s,
                       const float* __restrict__ lnc_b) {
    __shared__ float red[64];
    int j = blockIdx.x;
    int c = threadIdx.x;    // 0..63

    float m;
    float lns, lnb;
    if (j < 64) {
        m = w_q[c * 64 + j];
        lns = lnq_s[c]; lnb = lnq_b[c];
    } else if (j < 128) {
        m = w_kv[c * 128 + (j - 64)];
        lns = lnc_s[c]; lnb = lnc_b[c];
    } else {
        float s = 0.f;
        int jj = j - 128;
        #pragma unroll 8
        for (int t = 0; t < 64; t++)
            s += w_kv[c * 128 + 64 + t] * w_out[t * 64 + jj];
        m = s;
        lns = lnc_s[c]; lnb = lnc_b[c];
    }
    g_Wt2[(c >> 2) * 768 + j * 4 + (c & 3)] = lns * m;

    red[c] = lnb * m;
    __syncthreads();
    if (c < 32) {
        float v = red[c] + red[c + 32];
        #pragma unroll
        for (int o = 16; o > 0; o >>= 1) v += __shfl_xor_sync(~0u, v, o);
        if (c == 0) g_bc[j] = v;
    }
}

// ---------------------------------------------------------------------------
// K2: qkvo GEMM, asymmetric warp split (L1-wavefront optimized).
//   Block = 192 thr (6 warps), 64 positions.
//   Warps 0-3 (A): cols 64..191 (k|vo, ybuf=yc), ncol=4 per lane, 16 pos each.
//       per c: 4 LDS.128 + 4 dup + 32 FFMA2  (2x FLOP per LDS vs before)
//   Warps 4-5 (B): cols 0..63 (q, ybuf=yq), ncol=2 per lane, 32 pos each.
//       per c: 8 LDS.128 + 2 dup + 32 FFMA2
// ---------------------------------------------------------------------------
__global__ void __launch_bounds__(192, 3) k_qkvo() {
    __shared__ float yq[64 * YPAD];
    __shared__ float yc[64 * YPAD];
    int b  = blockIdx.x >> 8;           // 256 blocks per batch
    int pb = (blockIdx.x & 255) * 64;
    int tid = threadIdx.x;

    // yq tile: global rows [p][c] -> smem [c][p]
    const float* qrow = g_qf + ((size_t)b * N + pb) * 64;
    for (int idx = tid; idx < 4096; idx += 192) {
        int p = idx >> 6, c = idx & 63;
        yq[c * YPAD + p] = qrow[idx];
    }
    // yc tile: flat columns, already [c][p]
    const float* qb = g_qf + (size_t)b * N * 64;
    for (int idx = tid; idx < 4096; idx += 192) {
        int c = idx >> 6, p = idx & 63;
        yc[c * YPAD + p] = qb[(size_t)c * N + pb + p];
    }
    __syncthreads();

    // LN (normalize only; scale/bias folded into weights)
    if (tid < 128) {
        float* col = ((tid < 64) ? yq : yc) + (tid & 63);
        float s = 0.f, sq = 0.f;
        #pragma unroll 8
        for (int c = 0; c < 64; c++) { float v = col[c * YPAD]; s += v; sq += v * v; }
        float mu = s * (1.f / 64.f);
        float var = sq * (1.f / 64.f) - mu * mu;
        float rstd = rsqrtf(var + 1e-5f);
        #pragma unroll 8
        for (int c = 0; c < 64; c++) col[c * YPAD] = (col[c * YPAD] - mu) * rstd;
    }
    __syncthreads();

    int warp = tid >> 5;        // 0..5
    int lane = tid & 31;

    if (warp < 4) {
        // ---- A: k|vo, 4 cols per lane (j = 64+ci*32+lane), 16 positions ----
        int p0 = warp * 16;
        unsigned long long acc[4][8];
        #pragma unroll
        for (int ci = 0; ci < 4; ci++) {
            unsigned long long bv = dup_f32(__ldg(&g_bc[64 + ci * 32 + lane]));
            #pragma unroll
            for (int i = 0; i < 8; i++) acc[ci][i] = bv;
        }

        for (int c4 = 0; c4 < 16; c4++) {
            float4 w4[4];
            #pragma unroll
            for (int ci = 0; ci < 4; ci++)
                w4[ci] = __ldg((const float4*)&g_Wt2[c4 * 768 + (64 + ci * 32 + lane) * 4]);
            #pragma unroll
            for (int k = 0; k < 4; k++) {
                const float4* yp = (const float4*)&yc[(c4 * 4 + k) * YPAD + p0];
                float4 a0 = yp[0], a1 = yp[1], a2 = yp[2], a3 = yp[3];
                unsigned long long y0 = f2_to_ull(a0.x, a0.y);
                unsigned long long y1 = f2_to_ull(a0.z, a0.w);
                unsigned long long y2 = f2_to_ull(a1.x, a1.y);
                unsigned long long y3 = f2_to_ull(a1.z, a1.w);
                unsigned long long y4 = f2_to_ull(a2.x, a2.y);
                unsigned long long y5 = f2_to_ull(a2.z, a2.w);
                unsigned long long y6 = f2_to_ull(a3.x, a3.y);
                unsigned long long y7 = f2_to_ull(a3.z, a3.w);
                #pragma unroll
                for (int ci = 0; ci < 4; ci++) {
                    unsigned long long wv = dup_f32(((const float*)&w4[ci])[k]);
                    ffma2(acc[ci][0], y0, wv);
                    ffma2(acc[ci][1], y1, wv);
                    ffma2(acc[ci][2], y2, wv);
                    ffma2(acc[ci][3], y3, wv);
                    ffma2(acc[ci][4], y4, wv);
                    ffma2(acc[ci][5], y5, wv);
                    ffma2(acc[ci][6], y6, wv);
                    ffma2(acc[ci][7], y7, wv);
                }
            }
        }

        #pragma unroll
        for (int ci = 0; ci < 4; ci++) {
            int j = 64 + ci * 32 + lane;
            float* ob = g_qkvo + ((size_t)b * N + pb + p0) * 192 + j;
            #pragma unroll
            for (int i = 0; i < 8; i++) {
                float2 v = ull_to_f2(acc[ci][i]);
                ob[(size_t)(2 * i) * 192]     = v.x;
                ob[(size_t)(2 * i + 1) * 192] = v.y;
            }
        }
    } else {
        // ---- B: q, 2 cols per lane (j = lane, lane+32), 32 positions ----
        int p0 = (warp - 4) * 32;
        int jA = lane, jB = lane + 32;
        unsigned long long accA[16], accB[16];
        {
            unsigned long long bA = dup_f32(__ldg(&g_bc[jA]));
            unsigned long long bB = dup_f32(__ldg(&g_bc[jB]));
            #pragma unroll
            for (int i = 0; i < 16; i++) { accA[i] = bA; accB[i] = bB; }
        }

        for (int c4 = 0; c4 < 16; c4++) {
            float4 wA4 = __ldg((const float4*)&g_Wt2[c4 * 768 + jA * 4]);
            float4 wB4 = __ldg((const float4*)&g_Wt2[c4 * 768 + jB * 4]);
            const float* wAp = (const float*)&wA4;
            const float* wBp = (const float*)&wB4;
            #pragma unroll
            for (int k = 0; k < 4; k++) {
                unsigned long long wa = dup_f32(wAp[k]);
                unsigned long long wb = dup_f32(wBp[k]);
                const float4* yp = (const float4*)&yq[(c4 * 4 + k) * YPAD + p0];
                #pragma unroll
                for (int m = 0; m < 8; m++) {
                    float4 y4 = yp[m];
                    unsigned long long y01 = f2_to_ull(y4.x, y4.y);
                    unsigned long long y23 = f2_to_ull(y4.z, y4.w);
                    ffma2(accA[2 * m],     y01, wa);
                    ffma2(accA[2 * m + 1], y23, wa);
                    ffma2(accB[2 * m],     y01, wb);
                    ffma2(accB[2 * m + 1], y23, wb);
                }
            }
        }

        float* ob = g_qkvo + ((size_t)b * N + pb + p0) * 192;
        #pragma unroll
        for (int i = 0; i < 16; i++) {
            float2 a = ull_to_f2(accA[i]);
            float2 bv = ull_to_f2(accB[i]);
            ob[(size_t)(2 * i) * 192 + jA]     = a.x;
            ob[(size_t)(2 * i + 1) * 192 + jA] = a.y;
            ob[(size_t)(2 * i) * 192 + jB]     = bv.x;
            ob[(size_t)(2 * i + 1) * 192 + jB] = bv.y;
        }
    }
}

// ---------------------------------------------------------------------------
// K3: attention, 2D-tiled with smem halo.
//   Block = 256 thr (8 warps), tile = 4x8 queries, halo = 6x10 k|vo rows.
// ---------------------------------------------------------------------------
__global__ void __launch_bounds__(256) k_attn(const float* __restrict__ b_out,
                                              float* __restrict__ out) {
    __shared__ float kv[60 * 128];   // 30720 B
    int tile = blockIdx.x;           // 2048
    int b = tile >> 9;               // 512 tiles per batch
    int t = tile & 511;
    int th = t >> 4;                 // 0..31
    int tw = t & 15;                 // 0..15
    int h0 = th * 4, w0 = tw * 8;
    int tid = threadIdx.x;

    const float* kvb = g_qkvo + (size_t)b * N * 192;
    for (int i = tid; i < 1920; i += 256) {
        int r = i >> 5, q4 = i & 31;
        int ri = r / 10, rj = r % 10;
        int gh = min(max(h0 - 1 + ri, 0), H - 1);
        int gw = min(max(w0 - 1 + rj, 0), W - 1);
        ((float4*)kv)[r * 32 + q4] =
            *(const float4*)(kvb + (size_t)(gh * W + gw) * 192 + 64 + q4 * 4);
    }
    __syncthreads();

    int warp = tid >> 5, lane = tid & 31;
    int qi = warp >> 1;                    // 0..3
    float bo0 = __ldg(&b_out[lane]), bo1 = __ldg(&b_out[lane + 32]);

    #pragma unroll
    for (int q = 0; q < 4; q++) {
        int qj = (warp & 1) * 4 + q;       // 0..7
        int h = h0 + qi, w = w0 + qj;
        int g = b * N + h * W + w;
        const float* row = g_qkvo + (size_t)g * 192;
        float q0 = row[lane], q1 = row[32 + lane];

        int rr[9];
        float e[9];
        #pragma unroll
        for (int k = 0; k < 9; k++) {
            int di = k / 3 - 1, dj = k % 3 - 1;
            int nh = min(max(h + di, 0), H - 1) - h0 + 1;
            int nw = min(max(w + dj, 0), W - 1) - w0 + 1;
            rr[k] = nh * 10 + nw;
            const float* kr = kv + rr[k] * 128;
            float part = q0 * kr[lane] + q1 * kr[32 + lane];
            #pragma unroll
            for (int o = 1; o < 32; o <<= 1) part += __shfl_xor_sync(~0u, part, o);
            e[k] = part * 0.125f;
        }
        float m = e[0];
        #pragma unroll
        for (int k = 1; k < 9; k++) m = fmaxf(m, e[k]);
        float den = 0.f;
        #pragma unroll
        for (int k = 0; k < 9; k++) { e[k] = __expf(e[k] - m); den += e[k]; }
        float inv = 1.f / den;

        float o0 = 0.f, o1 = 0.f;
        #pragma unroll
        for (int k = 0; k < 9; k++) {
            const float* vr = kv + rr[k] * 128 + 64;
            float a = e[k] * inv;
            o0 += a * vr[lane];
            o1 += a * vr[32 + lane];
        }
        out[(size_t)g * OC + lane]      = o0 + bo0;
        out[(size_t)g * OC + 32 + lane] = o1 + bo1;
    }
}

// ---------------------------------------------------------------------------
// K4: tail — image sample, analytic fcoord sample, positional encoding.
// ---------------------------------------------------------------------------
__global__ void k_tail(const float* __restrict__ coords,
                       const float* __restrict__ image,
                       float* __restrict__ out) {
    int g = blockIdx.x * blockDim.x + threadIdx.x;
    if (g >= Bsz * N) return;
    int b = g >> 14;
    float y = coords[(size_t)g * 2 + 0];
    float x = coords[(size_t)g * 2 + 1];

    float ix = ((x + 1.f) * 256.f - 1.f) * 0.5f;
    float iy = ((y + 1.f) * 256.f - 1.f) * 0.5f;
    float x0f = floorf(ix), y0f = floorf(iy);
    float wx = ix - x0f, wy = iy - y0f;
    int x0 = (int)x0f, y0 = (int)y0f;
    const float* img = image + (size_t)b * 256 * 256;

    float ix2 = ((x + 1.f) * 128.f - 1.f) * 0.5f;
    float iy2 = ((y + 1.f) * 128.f - 1.f) * 0.5f;
    float x0f2 = floorf(ix2), y0f2 = floorf(iy2);
    float wx2 = ix2 - x0f2, wy2 = iy2 - y0f2;
    int x02 = (int)x0f2, y02 = (int)y0f2;

    float qin = 0.f, qcy = 0.f, qcx = 0.f;
    #pragma unroll
    for (int dy = 0; dy < 2; dy++) {
        #pragma unroll
        for (int dx = 0; dx < 2; dx++) {
            {
                int xc = x0 + dx, yc = y0 + dy;
                float wgt = (dx ? wx : 1.f - wx) * (dy ? wy : 1.f - wy);
                bool valid = (xc >= 0) && (xc < 256) && (yc >= 0) && (yc < 256);
                int xi = min(max(xc, 0), 255), yi = min(max(yc, 0), 255);
                qin += (valid ? wgt : 0.f) * img[yi * 256 + xi];
            }
            {
                int xc = x02 + dx, yc = y02 + dy;
                float wgt = (dx ? wx2 : 1.f - wx2) * (dy ? wy2 : 1.f - wy2);
                bool valid = (xc >= 0) && (xc < 128) && (yc >= 0) && (yc < 128);
                int xi = min(max(xc, 0), 127), yi = min(max(yc, 0), 127);
                float wv = valid ? wgt : 0.f;
                qcy += wv * (-1.f + (2.f * yi + 1.f) * (1.f / 128.f));
                qcx += wv * (-1.f + (2.f * xi + 1.f) * (1.f / 128.f));
            }
        }
    }

    float* o = out + (size_t)g * OC + 64;
    o[0] = qin;
    float cy = (qcy + 1.f) * 0.5f;
    float cx = (qcx + 1.f) * 0.5f;
    const float PI = 3.14159265358979323846f;
    #pragma unroll
    for (int k = 0; k < 6; k++) {
        float f = (float)(1 << k) * PI;
        float sy, cvy, sx, cvx;
        sincosf(cy * f, &sy, &cvy);
        sincosf(cx * f, &sx, &cvx);
        o[1 + k]          = sy;
        o[1 + 6 + k]      = sx;
        o[1 + 12 + k]     = cvy;
        o[1 + 12 + 6 + k] = cvx;
    }
}

extern "C" void kernel_launch(void* const* d_in, const int* in_sizes, int n_in,
                              void* d_out, int out_size) {
    const float* image   = (const float*)d_in[0];
    const float* latents = (const float*)d_in[1];
    const float* coords  = (const float*)d_in[2];
    const float* lnq_s   = (const float*)d_in[3];
    const float* lnq_b   = (const float*)d_in[4];
    const float* lnc_s   = (const float*)d_in[5];
    const float* lnc_b   = (const float*)d_in[6];
    const float* w_q     = (const float*)d_in[7];
    const float* w_kv    = (const float*)d_in[8];
    const float* w_out   = (const float*)d_in[9];
    const float* b_out   = (const float*)d_in[10];
    float* out = (float*)d_out;

    k_prep      <<<192, 64>>>(w_q, w_kv, w_out, lnq_s, lnq_b, lnc_s, lnc_b);
    k_transpose <<<1024, 256>>>(latents);
    k_sample_lat<<<8192, 256>>>(coords);
    k_qkvo      <<<1024, 192>>>();
    k_attn      <<<2048, 256>>>(b_out, out);
    k_tail      <<<256, 256>>>(coords, image, out);
}

// round 7
// speedup vs baseline: 1.0526x; 1.0497x over previous
#include <cuda_runtime.h>
#include <math.h>

#define Bsz 4
#define C 64
#define H 128
#define W 128
#define N 16384   // H*W per batch
#define OC 89
#define YPAD 68   // [c][p] tile pitch (floats); c*YPAD*4 is 16B-aligned

// scratch (__device__ globals; allocation is forbidden)
__device__ float g_lat_t[Bsz * N * C];    // latents channels-last [b][p][c]
__device__ float g_qf[Bsz * N * C];       // bilinear-sampled features [b][n][c]
__device__ float g_zyv[Bsz * N * 192];    // per row: zq[0:64] | yc[64:128] | vo[128:192]
// pre-duplicated folded weights: g_Wd[c2*128+j] = {w(2c2,j),w(2c2,j),w(2c2+1,j),w(2c2+1,j)}
__device__ ulonglong2 g_Wd[32 * 128];
__device__ float g_bias[128];             // GEMM bias: zq cols = w3, vo cols = 0
__device__ float g_bo[64];                // final output bias (beta_v@w_out + b_out)

// ---------------- f32x2 helpers (sm_103a packed fp32) ----------------------
__device__ __forceinline__ void ffma2(unsigned long long& d,
                                      unsigned long long a,
                                      unsigned long long b) {
    asm("fma.rn.f32x2 %0, %1, %2, %0;" : "+l"(d) : "l"(a), "l"(b));
}
__device__ __forceinline__ unsigned long long dup_f32(float v) {
    unsigned long long r;
    asm("mov.b64 %0, {%1, %1};" : "=l"(r) : "f"(v));
    return r;
}
__device__ __forceinline__ float2 ull_to_f2(unsigned long long v) {
    float2 r;
    asm("mov.b64 {%0, %1}, %2;" : "=f"(r.x), "=f"(r.y) : "l"(v));
    return r;
}

// ---------------------------------------------------------------------------
// K0: transpose latents [b][c][p] -> [b][p][c]
// ---------------------------------------------------------------------------
__global__ void k_transpose(const float* __restrict__ lat) {
    __shared__ float s[64][65];
    int b  = blockIdx.x >> 8;
    int pb = (blockIdx.x & 255) * 64;
    int tid = threadIdx.x;
    const float* src = lat + (size_t)b * N * C;
    {
        int pq = tid & 63, cg = tid >> 6;
        #pragma unroll
        for (int k = 0; k < 16; k++) {
            int c = cg * 16 + k;
            s[c][pq] = src[(size_t)c * N + pb + pq];
        }
    }
    __syncthreads();
    float* dst = g_lat_t + (size_t)b * N * C;
    {
        int cl = tid & 63, pg = tid >> 6;
        #pragma unroll
        for (int k = 0; k < 16; k++) {
            int p = pg * 16 + k;
            dst[(size_t)(pb + p) * C + cl] = s[cl][p];
        }
    }
}

// ---------------------------------------------------------------------------
// K1: bilinear sample of latents. One warp per point.
// ---------------------------------------------------------------------------
__global__ void k_sample_lat(const float* __restrict__ coords) {
    int gwarp = (blockIdx.x * blockDim.x + threadIdx.x) >> 5;
    int lane  = threadIdx.x & 31;
    if (gwarp >= Bsz * N) return;
    int b = gwarp >> 14;

    float y = coords[(size_t)gwarp * 2 + 0];   // xy = flip(coords)
    float x = coords[(size_t)gwarp * 2 + 1];
    float ix = ((x + 1.f) * (float)W - 1.f) * 0.5f;
    float iy = ((y + 1.f) * (float)H - 1.f) * 0.5f;
    float x0f = floorf(ix), y0f = floorf(iy);
    float wx1 = ix - x0f, wy1 = iy - y0f;
    int x0 = (int)x0f, y0 = (int)y0f;

    const float* base = g_lat_t + (size_t)b * N * C;
    float2 acc = make_float2(0.f, 0.f);
    #pragma unroll
    for (int dy = 0; dy < 2; dy++) {
        #pragma unroll
        for (int dx = 0; dx < 2; dx++) {
            int xc = x0 + dx, yc = y0 + dy;
            float wgt = (dx ? wx1 : 1.f - wx1) * (dy ? wy1 : 1.f - wy1);
            bool valid = (xc >= 0) && (xc < W) && (yc >= 0) && (yc < H);
            int xi = min(max(xc, 0), W - 1);
            int yi = min(max(yc, 0), H - 1);
            float wv = valid ? wgt : 0.f;
            float2 t = ((const float2*)(base + ((size_t)yi * W + xi) * C))[lane];
            acc.x += wv * t.x;
            acc.y += wv * t.y;
        }
    }
    ((float2*)(g_qf + (size_t)gwarp * C))[lane] = acc;
}

// ---------------------------------------------------------------------------
// k_prep: 128 blocks (one per GEMM column), 64 threads.
//   Col j<64  (zq):  Wf[c][j] = 0.125*lnq_s[c]*lnc_s[j]*dot(w_q[c,:], w_kv[j,0:64])
//                    bias[j]  = 0.125*lnc_s[j]*sum_t w_kv[j][t]*beta_q[t]
//                    beta_q[t] = sum_c lnq_b[c]*w_q[c][t]
//   Col j>=64 (vo):  Wf[c][j] = lnc_s[c]*sum_t w_kv[c][64+t]*w_out[t][j-64]
//                    bias[j]  = 0
//                    g_bo[j-64] = b_out[j-64] + sum_t beta_v[t]*w_out[t][j-64]
//                    beta_v[t] = sum_c lnc_b[c]*w_kv[c][64+t]
//   Weights stored pre-duplicated: g_Wd[c2*128+j] floats {w2c2,w2c2,w2c2+1,w2c2+1}
// ---------------------------------------------------------------------------
__global__ void k_prep(const float* __restrict__ w_q,
                       const float* __restrict__ w_kv,
                       const float* __restrict__ w_out,
                       const float* __restrict__ lnq_s,
                       const float* __restrict__ lnq_b,
                       const float* __restrict__ lnc_s,
                       const float* __restrict__ lnc_b,
                       const float* __restrict__ b_out) {
    __shared__ float red[64];
    int j = blockIdx.x;
    int t = threadIdx.x;    // doubles as channel index c
    float* Wf = (float*)g_Wd;

    if (j < 64) {
        // m = folded M[c][j]
        float s = 0.f;
        #pragma unroll 8
        for (int tt = 0; tt < 64; tt++)
            s += w_q[t * 64 + tt] * w_kv[j * 128 + tt];
        float m = 0.125f * lnq_s[t] * lnc_s[j] * s;
        int base = ((t >> 1) * 128 + j) * 4 + (t & 1) * 2;
        Wf[base] = m; Wf[base + 1] = m;

        // beta_q[t]
        float bq = 0.f;
        #pragma unroll 8
        for (int c = 0; c < 64; c++) bq += lnq_b[c] * w_q[c * 64 + t];
        red[t] = w_kv[j * 128 + t] * bq;
        __syncthreads();
        if (t < 32) {
            float v = red[t] + red[t + 32];
            #pragma unroll
            for (int o = 16; o > 0; o >>= 1) v += __shfl_xor_sync(~0u, v, o);
            if (t == 0) g_bias[j] = 0.125f * lnc_s[j] * v;
        }
    } else {
        int jj = j - 64;
        float s = 0.f;
        #pragma unroll 8
        for (int tt = 0; tt < 64; tt++)
            s += w_kv[t * 128 + 64 + tt] * w_out[tt * 64 + jj];
        float m = lnc_s[t] * s;
        int base = ((t >> 1) * 128 + j) * 4 + (t & 1) * 2;
        Wf[base] = m; Wf[base + 1] = m;

        // beta_v[t]
        float bv = 0.f;
        #pragma unroll 8
        for (int c = 0; c < 64; c++) bv += lnc_b[c] * w_kv[c * 128 + 64 + t];
        red[t] = bv * w_out[t * 64 + jj];
        __syncthreads();
        if (t < 32) {
            float v = red[t] + red[t + 32];
            #pragma unroll
            for (int o = 16; o > 0; o >>= 1) v += __shfl_xor_sync(~0u, v, o);
            if (t == 0) {
                g_bo[jj] = v + b_out[jj];
                g_bias[j] = 0.f;
            }
        }
    }
}

// ---------------------------------------------------------------------------
// K2: zq|vo GEMM + yc passthrough. Block = 128 thr (4 warps), 64 positions.
//   Warps 0,1: zq cols (lane j, j+32) from yq; warps 2,3: vo cols from yc.
//   Warp tile: 64 cols x 32 positions. Per c: 8 LDS.128 (ulonglong2 y-pairs)
//   + amortized 1 LDG.128 (pre-dup'd weight pair) + 32 FFMA2 -> 78% FMA.
// ---------------------------------------------------------------------------
__global__ void __launch_bounds__(128) k_zyv() {
    __shared__ float yq[64 * YPAD];
    __shared__ float yc[64 * YPAD];
    int b  = blockIdx.x >> 8;           // 256 blocks per batch
    int pb = (blockIdx.x & 255) * 64;
    int tid = threadIdx.x;

    // yq tile: global rows [p][c] -> smem [c][p], float4 reads
    const float4* qrow4 = (const float4*)(g_qf + ((size_t)b * N + pb) * 64);
    for (int idx = tid; idx < 1024; idx += 128) {
        int p = idx >> 4, c4 = idx & 15;
        float4 v = qrow4[idx];
        yq[(c4 * 4 + 0) * YPAD + p] = v.x;
        yq[(c4 * 4 + 1) * YPAD + p] = v.y;
        yq[(c4 * 4 + 2) * YPAD + p] = v.z;
        yq[(c4 * 4 + 3) * YPAD + p] = v.w;
    }
    // yc tile: flat columns, already [c][p], float4 reads+writes
    const float* qb = g_qf + (size_t)b * N * 64;
    for (int idx = tid; idx < 1024; idx += 128) {
        int c = idx >> 4, p4 = idx & 15;
        float4 v = *(const float4*)(qb + (size_t)c * N + pb + p4 * 4);
        *(float4*)&yc[c * YPAD + p4 * 4] = v;
    }
    __syncthreads();

    // LN (normalize only; all scales/biases folded into weights)
    if (tid < 128) {
        float* col = ((tid < 64) ? yq : yc) + (tid & 63);
        float s = 0.f, sq = 0.f;
        #pragma unroll 8
        for (int c = 0; c < 64; c++) { float v = col[c * YPAD]; s += v; sq += v * v; }
        float mu = s * (1.f / 64.f);
        float var = sq * (1.f / 64.f) - mu * mu;
        float rstd = rsqrtf(var + 1e-5f);
        #pragma unroll 8
        for (int c = 0; c < 64; c++) col[c * YPAD] = (col[c * YPAD] - mu) * rstd;
    }
    __syncthreads();

    int warp = tid >> 5, lane = tid & 31;
    bool isQ = warp < 2;
    int p0 = (warp & 1) * 32;
    const float* yb = isQ ? yq : yc;
    int jA = (isQ ? 0 : 64) + lane;     // GEMM col
    int jB = jA + 32;

    unsigned long long accA[16], accB[16];
    {
        unsigned long long bA = dup_f32(g_bias[jA]);
        unsigned long long bB = dup_f32(g_bias[jB]);
        #pragma unroll
        for (int i = 0; i < 16; i++) { accA[i] = bA; accB[i] = bB; }
    }

    #pragma unroll 4
    for (int c2 = 0; c2 < 32; c2++) {
        ulonglong2 wA = g_Wd[c2 * 128 + jA];   // .x = dup w(2c2,jA), .y = dup w(2c2+1,jA)
        ulonglong2 wB = g_Wd[c2 * 128 + jB];
        const ulonglong2* y0 = (const ulonglong2*)&yb[(2 * c2) * YPAD + p0];
        const ulonglong2* y1 = (const ulonglong2*)&yb[(2 * c2 + 1) * YPAD + p0];
        #pragma unroll
        for (int m = 0; m < 8; m++) {
            ulonglong2 u = y0[m];
            ffma2(accA[2 * m],     u.x, wA.x);
            ffma2(accA[2 * m + 1], u.y, wA.x);
            ffma2(accB[2 * m],     u.x, wB.x);
            ffma2(accB[2 * m + 1], u.y, wB.x);
        }
        #pragma unroll
        for (int m = 0; m < 8; m++) {
            ulonglong2 u = y1[m];
            ffma2(accA[2 * m],     u.x, wA.y);
            ffma2(accA[2 * m + 1], u.y, wA.y);
            ffma2(accB[2 * m],     u.x, wB.y);
            ffma2(accB[2 * m + 1], u.y, wB.y);
        }
    }

    // store: zq -> [0:64], vo -> [128:192]
    int sA = isQ ? jA : jA + 64;
    int sB = sA + 32;
    float* ob = g_zyv + ((size_t)b * N + pb + p0) * 192;
    #pragma unroll
    for (int i = 0; i < 16; i++) {
        float2 a = ull_to_f2(accA[i]);
        float2 bv = ull_to_f2(accB[i]);
        ob[(size_t)(2 * i) * 192 + sA]     = a.x;
        ob[(size_t)(2 * i + 1) * 192 + sA] = a.y;
        ob[(size_t)(2 * i) * 192 + sB]     = bv.x;
        ob[(size_t)(2 * i + 1) * 192 + sB] = bv.y;
    }

    // yc passthrough -> [64:128] (smem unchanged since LN sync)
    for (int idx = tid; idx < 4096; idx += 128) {
        int p = idx >> 6, c = idx & 63;
        g_zyv[((size_t)b * N + pb + p) * 192 + 64 + c] = yc[c * YPAD + p];
    }
}

// ---------------------------------------------------------------------------
// K3: attention, 2D-tiled with smem halo.
//   sim = zq . yc_nb (scale folded); o = sum a*vo_nb + g_bo.
// ---------------------------------------------------------------------------
__global__ void __launch_bounds__(256) k_attn(float* __restrict__ out) {
    __shared__ float kv[60 * 128];   // 30720 B: per halo row: yc[0:64] | vo[64:128]
    int tile = blockIdx.x;           // 2048
    int b = tile >> 9;
    int t = tile & 511;
    int th = t >> 4;
    int tw = t & 15;
    int h0 = th * 4, w0 = tw * 8;
    int tid = threadIdx.x;

    const float* kvb = g_zyv + (size_t)b * N * 192;
    for (int i = tid; i < 1920; i += 256) {
        int r = i >> 5, q4 = i & 31;
        int ri = r / 10, rj = r % 10;
        int gh = min(max(h0 - 1 + ri, 0), H - 1);
        int gw = min(max(w0 - 1 + rj, 0), W - 1);
        ((float4*)kv)[r * 32 + q4] =
            *(const float4*)(kvb + (size_t)(gh * W + gw) * 192 + 64 + q4 * 4);
    }
    __syncthreads();

    int warp = tid >> 5, lane = tid & 31;
    int qi = warp >> 1;
    float bo0 = g_bo[lane], bo1 = g_bo[lane + 32];

    #pragma unroll
    for (int q = 0; q < 4; q++) {
        int qj = (warp & 1) * 4 + q;
        int h = h0 + qi, w = w0 + qj;
        int g = b * N + h * W + w;
        const float* row = g_zyv + (size_t)g * 192;
        float q0 = row[lane], q1 = row[32 + lane];   // zq

        int rr[9];
        float e[9];
        #pragma unroll
        for (int k = 0; k < 9; k++) {
            int di = k / 3 - 1, dj = k % 3 - 1;
            int nh = min(max(h + di, 0), H - 1) - h0 + 1;
            int nw = min(max(w + dj, 0), W - 1) - w0 + 1;
            rr[k] = nh * 10 + nw;
            const float* kr = kv + rr[k] * 128;      // yc of neighbor
            float part = q0 * kr[lane] + q1 * kr[32 + lane];
            #pragma unroll
            for (int o = 1; o < 32; o <<= 1) part += __shfl_xor_sync(~0u, part, o);
            e[k] = part;                              // scale folded into zq
        }
        float m = e[0];
        #pragma unroll
        for (int k = 1; k < 9; k++) m = fmaxf(m, e[k]);
        float den = 0.f;
        #pragma unroll
        for (int k = 0; k < 9; k++) { e[k] = __expf(e[k] - m); den += e[k]; }
        float inv = 1.f / den;

        float o0 = 0.f, o1 = 0.f;
        #pragma unroll
        for (int k = 0; k < 9; k++) {
            const float* vr = kv + rr[k] * 128 + 64;  // vo of neighbor
            float a = e[k] * inv;
            o0 += a * vr[lane];
            o1 += a * vr[32 + lane];
        }
        out[(size_t)g * OC + lane]      = o0 + bo0;
        out[(size_t)g * OC + 32 + lane] = o1 + bo1;
    }
}

// ---------------------------------------------------------------------------
// K4: tail — image sample, analytic fcoord sample, positional encoding.
// ---------------------------------------------------------------------------
__global__ void k_tail(const float* __restrict__ coords,
                       const float* __restrict__ image,
                       float* __restrict__ out) {
    int g = blockIdx.x * blockDim.x + threadIdx.x;
    if (g >= Bsz * N) return;
    int b = g >> 14;
    float y = coords[(size_t)g * 2 + 0];
    float x = coords[(size_t)g * 2 + 1];

    float ix = ((x + 1.f) * 256.f - 1.f) * 0.5f;
    float iy = ((y + 1.f) * 256.f - 1.f) * 0.5f;
    float x0f = floorf(ix), y0f = floorf(iy);
    float wx = ix - x0f, wy = iy - y0f;
    int x0 = (int)x0f, y0 = (int)y0f;
    const float* img = image + (size_t)b * 256 * 256;

    float ix2 = ((x + 1.f) * 128.f - 1.f) * 0.5f;
    float iy2 = ((y + 1.f) * 128.f - 1.f) * 0.5f;
    float x0f2 = floorf(ix2), y0f2 = floorf(iy2);
    float wx2 = ix2 - x0f2, wy2 = iy2 - y0f2;
    int x02 = (int)x0f2, y02 = (int)y0f2;

    float qin = 0.f, qcy = 0.f, qcx = 0.f;
    #pragma unroll
    for (int dy = 0; dy < 2; dy++) {
        #pragma unroll
        for (int dx = 0; dx < 2; dx++) {
            {
                int xc = x0 + dx, yc = y0 + dy;
                float wgt = (dx ? wx : 1.f - wx) * (dy ? wy : 1.f - wy);
                bool valid = (xc >= 0) && (xc < 256) && (yc >= 0) && (yc < 256);
                int xi = min(max(xc, 0), 255), yi = min(max(yc, 0), 255);
                qin += (valid ? wgt : 0.f) * img[yi * 256 + xi];
            }
            {
                int xc = x02 + dx, yc = y02 + dy;
                float wgt = (dx ? wx2 : 1.f - wx2) * (dy ? wy2 : 1.f - wy2);
                bool valid = (xc >= 0) && (xc < 128) && (yc >= 0) && (yc < 128);
                int xi = min(max(xc, 0), 127), yi = min(max(yc, 0), 127);
                float wv = valid ? wgt : 0.f;
                qcy += wv * (-1.f + (2.f * yi + 1.f) * (1.f / 128.f));
                qcx += wv * (-1.f + (2.f * xi + 1.f) * (1.f / 128.f));
            }
        }
    }

    float* o = out + (size_t)g * OC + 64;
    o[0] = qin;
    float cy = (qcy + 1.f) * 0.5f;
    float cx = (qcx + 1.f) * 0.5f;
    const float PI = 3.14159265358979323846f;
    #pragma unroll
    for (int k = 0; k < 6; k++) {
        float f = (float)(1 << k) * PI;
        float sy, cvy, sx, cvx;
        sincosf(cy * f, &sy, &cvy);
        sincosf(cx * f, &sx, &cvx);
        o[1 + k]          = sy;
        o[1 + 6 + k]      = sx;
        o[1 + 12 + k]     = cvy;
        o[1 + 12 + 6 + k] = cvx;
    }
}

extern "C" void kernel_launch(void* const* d_in, const int* in_sizes, int n_in,
                              void* d_out, int out_size) {
    const float* image   = (const float*)d_in[0];
    const float* latents = (const float*)d_in[1];
    const float* coords  = (const float*)d_in[2];
    const float* lnq_s   = (const float*)d_in[3];
    const float* lnq_b   = (const float*)d_in[4];
    const float* lnc_s   = (const float*)d_in[5];
    const float* lnc_b   = (const float*)d_in[6];
    const float* w_q     = (const float*)d_in[7];
    const float* w_kv    = (const float*)d_in[8];
    const float* w_out   = (const float*)d_in[9];
    const float* b_out   = (const float*)d_in[10];
    float* out = (float*)d_out;

    k_prep      <<<128, 64>>>(w_q, w_kv, w_out, lnq_s, lnq_b, lnc_s, lnc_b, b_out);
    k_transpose <<<1024, 256>>>(latents);
    k_sample_lat<<<8192, 256>>>(coords);
    k_zyv       <<<1024, 128>>>();
    k_attn      <<<2048, 256>>>(out);
    k_tail      <<<256, 256>>>(coords, image, out);
}